// round 3
// baseline (speedup 1.0000x reference)
#include <cuda_runtime.h>
#include <stdint.h>

#define NN 50000
#define NE 800000
#define NG 256
#define INDIM 300
#define HID 256

// ---------------- scratch (device globals; no allocation allowed) ----------------
__device__ __align__(16) float g_t[(size_t)NN * HID];   // transformed (h @ W)
__device__ __align__(16) float g_a[(size_t)NN * HID];   // aggregated output
__device__ float g_dinv[NN];
__device__ int   g_cnt[NN];
__device__ int   g_rowptr[NN + 1];
__device__ int   g_cursor[NN];
__device__ int   g_csr_src[NE];
__device__ float g_csr_w[NE];
__device__ float g_pooled[NG * HID];

// ---------------- graph preprocessing ----------------
__global__ void k_zero() {
    int i = blockIdx.x * blockDim.x + threadIdx.x;
    if (i < NN) { g_cnt[i] = 0; g_cursor[i] = 0; }
}

// edge_index is int32 (JAX x64 disabled): ei[0..NE) = src, ei[NE..2NE) = dst
__global__ void k_hist(const int* __restrict__ ei) {
    int e = blockIdx.x * blockDim.x + threadIdx.x;
    if (e < NE) {
        int d = ei[NE + e];
        if (d >= 0 && d < NN) atomicAdd(&g_cnt[d], 1);
    }
}

// single-block exclusive scan over g_cnt -> g_rowptr
__global__ void k_scan() {
    const int CH = (NN + 1023) / 1024;  // 49
    __shared__ int part[1024];
    int t = threadIdx.x;
    int begin = t * CH;
    int end = begin + CH; if (end > NN) end = NN; if (begin > NN) begin = NN;
    int s = 0;
    for (int i = begin; i < end; i++) s += g_cnt[i];
    part[t] = s;
    __syncthreads();
    if (t == 0) {
        int run = 0;
        for (int i = 0; i < 1024; i++) { int v = part[i]; part[i] = run; run += v; }
    }
    __syncthreads();
    int run = part[t];
    for (int i = begin; i < end; i++) { g_rowptr[i] = run; run += g_cnt[i]; }
    if (t == 1023) g_rowptr[NN] = run;
}

__global__ void k_dinv() {
    int i = blockIdx.x * blockDim.x + threadIdx.x;
    if (i < NN) g_dinv[i] = rsqrtf((float)(g_cnt[i] + 1));  // +1 self-loop
}

__global__ void k_build(const int* __restrict__ ei) {
    int e = blockIdx.x * blockDim.x + threadIdx.x;
    if (e >= NE) return;
    int s = ei[e];
    int d = ei[NE + e];
    if (s < 0 || s >= NN || d < 0 || d >= NN) return;
    int pos = g_rowptr[d] + atomicAdd(&g_cursor[d], 1);
    g_csr_src[pos] = s;
    g_csr_w[pos] = g_dinv[s] * g_dinv[d];
}

// ---------------- GEMM: g_t[M,256] = A[M,K] @ B[K,256] (row-major) ----------------
// A = x (external) when use_ext=1, else g_a. 64x64 tile, BK=16, 256 thr, 4x4 micro.
__global__ void k_gemm(const float* __restrict__ Aext, int use_ext,
                       const float* __restrict__ B, int K) {
    const float* A = use_ext ? Aext : (const float*)g_a;
    __shared__ float As[16][65];
    __shared__ float Bs[16][64];
    int bm = blockIdx.y * 64, bn = blockIdx.x * 64;
    int tid = threadIdx.x;
    int tr = tid >> 4, tc = tid & 15;
    float acc[4][4] = {};

    for (int k0 = 0; k0 < K; k0 += 16) {
        // A tile: each thread loads 4 consecutive K-elements of one row
        int row = tid >> 2;
        int x = (tid & 3) * 4;
        int gr = bm + row;
        if (gr < NN && (k0 + x + 3) < K) {
            float4 v = *(const float4*)(A + (size_t)gr * K + k0 + x);
            As[x + 0][row] = v.x; As[x + 1][row] = v.y;
            As[x + 2][row] = v.z; As[x + 3][row] = v.w;
        } else {
            #pragma unroll
            for (int j = 0; j < 4; j++) {
                int kk = k0 + x + j;
                As[x + j][row] = (gr < NN && kk < K) ? A[(size_t)gr * K + kk] : 0.f;
            }
        }
        // B tile
        #pragma unroll
        for (int i = 0; i < 4; i++) {
            int j = tid + 256 * i;
            int kk = j >> 6, c = j & 63;
            int gk = k0 + kk;
            Bs[kk][c] = (gk < K) ? B[(size_t)gk * 256 + bn + c] : 0.f;
        }
        __syncthreads();
        #pragma unroll
        for (int kk = 0; kk < 16; kk++) {
            float ra[4], rb[4];
            #pragma unroll
            for (int i = 0; i < 4; i++) ra[i] = As[kk][tr * 4 + i];
            #pragma unroll
            for (int j = 0; j < 4; j++) rb[j] = Bs[kk][tc * 4 + j];
            #pragma unroll
            for (int i = 0; i < 4; i++)
                #pragma unroll
                for (int j = 0; j < 4; j++)
                    acc[i][j] += ra[i] * rb[j];
        }
        __syncthreads();
    }
    #pragma unroll
    for (int i = 0; i < 4; i++) {
        int gr = bm + tr * 4 + i;
        if (gr < NN) {
            #pragma unroll
            for (int j = 0; j < 4; j++)
                g_t[(size_t)gr * 256 + bn + tc * 4 + j] = acc[i][j];
        }
    }
}

// ---------------- aggregation: g_a[d] = sum_e norm*g_t[src] + dinv^2*g_t[d] + b ----------------
// one warp per node; lane holds cols [4*lane,4*lane+4) and [128+4*lane, ...)
__global__ void k_agg(const float* __restrict__ bias, int relu) {
    int gw = (blockIdx.x * blockDim.x + threadIdx.x) >> 5;
    int lane = threadIdx.x & 31;
    if (gw >= NN) return;
    int n = gw;
    float dn = g_dinv[n];
    float sw = dn * dn;
    const float4* trow = (const float4*)(g_t + (size_t)n * 256);
    float4 a0 = trow[lane], a1 = trow[lane + 32];
    a0.x *= sw; a0.y *= sw; a0.z *= sw; a0.w *= sw;
    a1.x *= sw; a1.y *= sw; a1.z *= sw; a1.w *= sw;
    int beg = g_rowptr[n], end = g_rowptr[n + 1];
    for (int i = beg; i < end; i++) {
        int s = g_csr_src[i];
        float w = g_csr_w[i];
        const float4* srow = (const float4*)(g_t + (size_t)s * 256);
        float4 v0 = srow[lane], v1 = srow[lane + 32];
        a0.x += w * v0.x; a0.y += w * v0.y; a0.z += w * v0.z; a0.w += w * v0.w;
        a1.x += w * v1.x; a1.y += w * v1.y; a1.z += w * v1.z; a1.w += w * v1.w;
    }
    float4 b0 = ((const float4*)bias)[lane];
    float4 b1 = ((const float4*)bias)[lane + 32];
    a0.x += b0.x; a0.y += b0.y; a0.z += b0.z; a0.w += b0.w;
    a1.x += b1.x; a1.y += b1.y; a1.z += b1.z; a1.w += b1.w;
    if (relu) {
        a0.x = fmaxf(a0.x, 0.f); a0.y = fmaxf(a0.y, 0.f);
        a0.z = fmaxf(a0.z, 0.f); a0.w = fmaxf(a0.w, 0.f);
        a1.x = fmaxf(a1.x, 0.f); a1.y = fmaxf(a1.y, 0.f);
        a1.z = fmaxf(a1.z, 0.f); a1.w = fmaxf(a1.w, 0.f);
    }
    float4* orow = (float4*)(g_a + (size_t)n * 256);
    orow[lane] = a0; orow[lane + 32] = a1;
}

// ---------------- global mean pool (batch is sorted int32) ----------------
__global__ void k_pool(const int* __restrict__ batch) {
    int g = blockIdx.x;
    int c = threadIdx.x;  // 256 threads
    __shared__ int slo, shi;
    if (c == 0) {
        int l = 0, r = NN;
        while (l < r) { int m = (l + r) >> 1; if (batch[m] < g) l = m + 1; else r = m; }
        slo = l;
        l = 0; r = NN;
        while (l < r) { int m = (l + r) >> 1; if (batch[m] < g + 1) l = m + 1; else r = m; }
        shi = l;
    }
    __syncthreads();
    int lo = slo, hi = shi;
    float s = 0.f;
    for (int n = lo; n < hi; n++) s += g_a[(size_t)n * 256 + c];
    int cnt = hi - lo;
    float inv = (cnt > 0) ? (1.0f / (float)cnt) : 1.0f;
    g_pooled[g * 256 + c] = s * inv;
}

// ---------------- classifier: one block per graph ----------------
__global__ void k_cls(const float* __restrict__ Wc1, const float* __restrict__ bc1,
                      const float* __restrict__ Wc2, const float* __restrict__ bc2,
                      const float* __restrict__ Wc3, const float* __restrict__ bc3,
                      float* __restrict__ out) {
    int g = blockIdx.x, t = threadIdx.x;
    __shared__ float p[256], q1[16], q2[64];
    p[t] = g_pooled[g * 256 + t];
    __syncthreads();
    float* o1 = out;                         // [256,16]
    float* o2 = out + 256 * 16;              // [256,64]
    float* o3 = out + 256 * 16 + 256 * 64;   // [256,256]

    if (t < 16) {
        float s = bc1[t];
        for (int k = 0; k < 256; k++) s += p[k] * Wc1[k * 16 + t];
        q1[t] = s;
        o1[g * 16 + t] = s;
    }
    __syncthreads();
    if (t == 0) {
        float m = q1[0];
        for (int i = 1; i < 16; i++) m = fmaxf(m, q1[i]);
        float sum = 0.f;
        for (int i = 0; i < 16; i++) { q1[i] = expf(q1[i] - m); sum += q1[i]; }
        float inv = 1.f / sum;
        for (int i = 0; i < 16; i++) q1[i] *= inv;
    }
    __syncthreads();
    if (t < 64) {
        float s = bc2[t];
        for (int k = 0; k < 256; k++) s += p[k] * Wc2[k * 64 + t];
        for (int k = 0; k < 16; k++) s += q1[k] * Wc2[(256 + k) * 64 + t];
        q2[t] = s;
        o2[g * 64 + t] = s;
    }
    __syncthreads();
    if (t == 0) {
        float m = q2[0];
        for (int i = 1; i < 64; i++) m = fmaxf(m, q2[i]);
        float sum = 0.f;
        for (int i = 0; i < 64; i++) { q2[i] = expf(q2[i] - m); sum += q2[i]; }
        float inv = 1.f / sum;
        for (int i = 0; i < 64; i++) q2[i] *= inv;
    }
    __syncthreads();
    {
        float s = bc3[t];
        for (int k = 0; k < 256; k++) s += p[k] * Wc3[k * 256 + t];
        for (int k = 0; k < 64; k++) s += q2[k] * Wc3[(256 + k) * 256 + t];
        o3[g * 256 + t] = s;
    }
}

// ---------------- launch ----------------
extern "C" void kernel_launch(void* const* d_in, const int* in_sizes, int n_in,
                              void* d_out, int out_size) {
    const float* x     = (const float*)d_in[0];
    const int*   ei    = (const int*)d_in[1];    // int32 (JAX x64 off)
    const int*   batch = (const int*)d_in[2];    // int32
    const float* W1 = (const float*)d_in[3],  *b1 = (const float*)d_in[4];
    const float* W2 = (const float*)d_in[5],  *b2 = (const float*)d_in[6];
    const float* W3 = (const float*)d_in[7],  *b3 = (const float*)d_in[8];
    const float* Wc1 = (const float*)d_in[9],  *bc1 = (const float*)d_in[10];
    const float* Wc2 = (const float*)d_in[11], *bc2 = (const float*)d_in[12];
    const float* Wc3 = (const float*)d_in[13], *bc3 = (const float*)d_in[14];
    float* out = (float*)d_out;

    // graph preprocessing (rebuilt every call: deterministic, no caching)
    k_zero<<<(NN + 255) / 256, 256>>>();
    k_hist<<<NE / 256, 256>>>(ei);
    k_scan<<<1, 1024>>>();
    k_dinv<<<(NN + 255) / 256, 256>>>();
    k_build<<<NE / 256, 256>>>(ei);

    dim3 gg(256 / 64, (NN + 63) / 64);  // (4, 782)
    // layer 1
    k_gemm<<<gg, 256>>>(x, 1, W1, INDIM);
    k_agg<<<(NN * 32) / 256, 256>>>(b1, 1);
    // layer 2
    k_gemm<<<gg, 256>>>(nullptr, 0, W2, HID);
    k_agg<<<(NN * 32) / 256, 256>>>(b2, 1);
    // layer 3
    k_gemm<<<gg, 256>>>(nullptr, 0, W3, HID);
    k_agg<<<(NN * 32) / 256, 256>>>(b3, 0);

    k_pool<<<NG, 256>>>(batch);
    k_cls<<<NG, 256>>>(Wc1, bc1, Wc2, bc2, Wc3, bc3, out);
}

// round 4
// speedup vs baseline: 1.3311x; 1.3311x over previous
#include <cuda_runtime.h>
#include <stdint.h>

#define NN 50000
#define NE 800000
#define NG 256
#define INDIM 300
#define HID 256

// ---------------- scratch (device globals; no allocation allowed) ----------------
__device__ __align__(16) float g_t[(size_t)NN * HID];   // transformed (h @ W)
__device__ __align__(16) float g_a[(size_t)NN * HID];   // aggregated output
__device__ float g_dinv[NN];
__device__ int   g_cnt[NN];
__device__ int   g_rowptr[NN + 1];
__device__ int   g_cursor[NN];
__device__ int   g_csr_src[NE];
__device__ float g_csr_w[NE];
__device__ float g_pooled[NG * HID];

// ---------------- graph preprocessing ----------------
__global__ void k_zero() {
    int i = blockIdx.x * blockDim.x + threadIdx.x;
    if (i < NN) { g_cnt[i] = 0; g_cursor[i] = 0; }
}

__global__ void k_hist(const int* __restrict__ ei) {
    int e = blockIdx.x * blockDim.x + threadIdx.x;
    if (e < NE) {
        int d = ei[NE + e];
        if (d >= 0 && d < NN) atomicAdd(&g_cnt[d], 1);
    }
}

__global__ void k_scan() {
    const int CH = (NN + 1023) / 1024;  // 49
    __shared__ int part[1024];
    int t = threadIdx.x;
    int begin = t * CH;
    int end = begin + CH; if (end > NN) end = NN; if (begin > NN) begin = NN;
    int s = 0;
    for (int i = begin; i < end; i++) s += g_cnt[i];
    part[t] = s;
    __syncthreads();
    if (t == 0) {
        int run = 0;
        for (int i = 0; i < 1024; i++) { int v = part[i]; part[i] = run; run += v; }
    }
    __syncthreads();
    int run = part[t];
    for (int i = begin; i < end; i++) { g_rowptr[i] = run; run += g_cnt[i]; }
    if (t == 1023) g_rowptr[NN] = run;
}

__global__ void k_dinv() {
    int i = blockIdx.x * blockDim.x + threadIdx.x;
    if (i < NN) g_dinv[i] = rsqrtf((float)(g_cnt[i] + 1));
}

__global__ void k_build(const int* __restrict__ ei) {
    int e = blockIdx.x * blockDim.x + threadIdx.x;
    if (e >= NE) return;
    int s = ei[e];
    int d = ei[NE + e];
    if (s < 0 || s >= NN || d < 0 || d >= NN) return;
    int pos = g_rowptr[d] + atomicAdd(&g_cursor[d], 1);
    g_csr_src[pos] = s;
    g_csr_w[pos] = g_dinv[s] * g_dinv[d];
}

// ---------------- tf32 tensor-core GEMM: g_t[M,256] = A[M,K] @ B[K,256] ----------------
__device__ __forceinline__ uint32_t f2tf32(float x) {
    uint32_t r;
    asm("cvt.rna.tf32.f32 %0, %1;" : "=r"(r) : "f"(x));
    return r;
}

// block tile 128x128, BK=16, 256 threads = 8 warps (4x2), warp tile 32x64
__global__ void __launch_bounds__(256) k_gemm_tc(const float* __restrict__ Aext, int use_ext,
                                                 const float* __restrict__ B, int K) {
    const float* A = use_ext ? Aext : (const float*)g_a;
    __shared__ uint32_t As[128][20];   // [m][k], pad 20 -> conflict-free frag loads
    __shared__ uint32_t Bs[16][136];   // [k][n], pad 136 -> conflict-free frag loads

    int bm = blockIdx.y * 128, bn = blockIdx.x * 128;
    int tid = threadIdx.x;
    int wid = tid >> 5, lane = tid & 31;
    int wr = wid >> 1, wc = wid & 1;           // warp rows [wr*32,+32), cols [wc*64,+64)
    int gid = lane >> 2, tig = lane & 3;

    float acc[2][8][4];
    #pragma unroll
    for (int i = 0; i < 2; i++)
        #pragma unroll
        for (int j = 0; j < 8; j++)
            #pragma unroll
            for (int l = 0; l < 4; l++) acc[i][j][l] = 0.f;

    for (int k0 = 0; k0 < K; k0 += 16) {
        // ---- A tile: 128 rows x 16 k; 512 float4, 2 per thread ----
        #pragma unroll
        for (int i = 0; i < 2; i++) {
            int idx = tid + 256 * i;
            int row = idx >> 2;
            int kq = (idx & 3) << 2;
            int grow = bm + row;
            uint32_t v0 = 0, v1 = 0, v2 = 0, v3 = 0;
            if (grow < NN) {
                if (k0 + kq + 4 <= K) {
                    float4 v = *(const float4*)(A + (size_t)grow * K + k0 + kq);
                    v0 = f2tf32(v.x); v1 = f2tf32(v.y); v2 = f2tf32(v.z); v3 = f2tf32(v.w);
                } else {
                    float t0 = (k0 + kq + 0 < K) ? A[(size_t)grow * K + k0 + kq + 0] : 0.f;
                    float t1 = (k0 + kq + 1 < K) ? A[(size_t)grow * K + k0 + kq + 1] : 0.f;
                    float t2 = (k0 + kq + 2 < K) ? A[(size_t)grow * K + k0 + kq + 2] : 0.f;
                    float t3 = (k0 + kq + 3 < K) ? A[(size_t)grow * K + k0 + kq + 3] : 0.f;
                    v0 = f2tf32(t0); v1 = f2tf32(t1); v2 = f2tf32(t2); v3 = f2tf32(t3);
                }
            }
            As[row][kq + 0] = v0; As[row][kq + 1] = v1;
            As[row][kq + 2] = v2; As[row][kq + 3] = v3;
        }
        // ---- B tile: 16 k x 128 n; 512 float4, 2 per thread ----
        #pragma unroll
        for (int i = 0; i < 2; i++) {
            int idx = tid + 256 * i;
            int kk = idx >> 5;
            int n4 = (idx & 31) << 2;
            int gk = k0 + kk;
            uint32_t v0 = 0, v1 = 0, v2 = 0, v3 = 0;
            if (gk < K) {
                float4 v = *(const float4*)(B + (size_t)gk * 256 + bn + n4);
                v0 = f2tf32(v.x); v1 = f2tf32(v.y); v2 = f2tf32(v.z); v3 = f2tf32(v.w);
            }
            Bs[kk][n4 + 0] = v0; Bs[kk][n4 + 1] = v1;
            Bs[kk][n4 + 2] = v2; Bs[kk][n4 + 3] = v3;
        }
        __syncthreads();

        #pragma unroll
        for (int ks = 0; ks < 16; ks += 8) {
            uint32_t a[2][4], b[8][2];
            #pragma unroll
            for (int mt = 0; mt < 2; mt++) {
                int r = wr * 32 + mt * 16;
                a[mt][0] = As[r + gid][ks + tig];
                a[mt][1] = As[r + gid + 8][ks + tig];
                a[mt][2] = As[r + gid][ks + tig + 4];
                a[mt][3] = As[r + gid + 8][ks + tig + 4];
            }
            #pragma unroll
            for (int nt = 0; nt < 8; nt++) {
                int c = wc * 64 + nt * 8 + gid;
                b[nt][0] = Bs[ks + tig][c];
                b[nt][1] = Bs[ks + tig + 4][c];
            }
            #pragma unroll
            for (int mt = 0; mt < 2; mt++)
                #pragma unroll
                for (int nt = 0; nt < 8; nt++) {
                    asm volatile(
                        "mma.sync.aligned.m16n8k8.row.col.f32.tf32.tf32.f32 "
                        "{%0,%1,%2,%3}, {%4,%5,%6,%7}, {%8,%9}, {%0,%1,%2,%3};"
                        : "+f"(acc[mt][nt][0]), "+f"(acc[mt][nt][1]),
                          "+f"(acc[mt][nt][2]), "+f"(acc[mt][nt][3])
                        : "r"(a[mt][0]), "r"(a[mt][1]), "r"(a[mt][2]), "r"(a[mt][3]),
                          "r"(b[nt][0]), "r"(b[nt][1]));
                }
        }
        __syncthreads();
    }

    // ---- store ----
    #pragma unroll
    for (int mt = 0; mt < 2; mt++) {
        #pragma unroll
        for (int nt = 0; nt < 8; nt++) {
            int r0 = bm + wr * 32 + mt * 16 + gid;
            int cc = bn + wc * 64 + nt * 8 + tig * 2;
            if (r0 < NN) {
                float2 v; v.x = acc[mt][nt][0]; v.y = acc[mt][nt][1];
                *(float2*)(g_t + (size_t)r0 * 256 + cc) = v;
            }
            if (r0 + 8 < NN) {
                float2 v; v.x = acc[mt][nt][2]; v.y = acc[mt][nt][3];
                *(float2*)(g_t + (size_t)(r0 + 8) * 256 + cc) = v;
            }
        }
    }
}

// ---------------- aggregation ----------------
__global__ void k_agg(const float* __restrict__ bias, int relu) {
    int gw = (blockIdx.x * blockDim.x + threadIdx.x) >> 5;
    int lane = threadIdx.x & 31;
    if (gw >= NN) return;
    int n = gw;
    float dn = g_dinv[n];
    float sw = dn * dn;
    const float4* trow = (const float4*)(g_t + (size_t)n * 256);
    float4 a0 = trow[lane], a1 = trow[lane + 32];
    a0.x *= sw; a0.y *= sw; a0.z *= sw; a0.w *= sw;
    a1.x *= sw; a1.y *= sw; a1.z *= sw; a1.w *= sw;
    int beg = g_rowptr[n], end = g_rowptr[n + 1];
    for (int i = beg; i < end; i++) {
        int s = g_csr_src[i];
        float w = g_csr_w[i];
        const float4* srow = (const float4*)(g_t + (size_t)s * 256);
        float4 v0 = srow[lane], v1 = srow[lane + 32];
        a0.x += w * v0.x; a0.y += w * v0.y; a0.z += w * v0.z; a0.w += w * v0.w;
        a1.x += w * v1.x; a1.y += w * v1.y; a1.z += w * v1.z; a1.w += w * v1.w;
    }
    float4 b0 = ((const float4*)bias)[lane];
    float4 b1 = ((const float4*)bias)[lane + 32];
    a0.x += b0.x; a0.y += b0.y; a0.z += b0.z; a0.w += b0.w;
    a1.x += b1.x; a1.y += b1.y; a1.z += b1.z; a1.w += b1.w;
    if (relu) {
        a0.x = fmaxf(a0.x, 0.f); a0.y = fmaxf(a0.y, 0.f);
        a0.z = fmaxf(a0.z, 0.f); a0.w = fmaxf(a0.w, 0.f);
        a1.x = fmaxf(a1.x, 0.f); a1.y = fmaxf(a1.y, 0.f);
        a1.z = fmaxf(a1.z, 0.f); a1.w = fmaxf(a1.w, 0.f);
    }
    float4* orow = (float4*)(g_a + (size_t)n * 256);
    orow[lane] = a0; orow[lane + 32] = a1;
}

// ---------------- global mean pool (batch is sorted int32) ----------------
__global__ void k_pool(const int* __restrict__ batch) {
    int g = blockIdx.x;
    int c = threadIdx.x;  // 256 threads
    __shared__ int slo, shi;
    if (c == 0) {
        int l = 0, r = NN;
        while (l < r) { int m = (l + r) >> 1; if (batch[m] < g) l = m + 1; else r = m; }
        slo = l;
        l = 0; r = NN;
        while (l < r) { int m = (l + r) >> 1; if (batch[m] < g + 1) l = m + 1; else r = m; }
        shi = l;
    }
    __syncthreads();
    int lo = slo, hi = shi;
    float s = 0.f;
    for (int n = lo; n < hi; n++) s += g_a[(size_t)n * 256 + c];
    int cnt = hi - lo;
    float inv = (cnt > 0) ? (1.0f / (float)cnt) : 1.0f;
    g_pooled[g * 256 + c] = s * inv;
}

// ---------------- classifier: one block per graph ----------------
__global__ void k_cls(const float* __restrict__ Wc1, const float* __restrict__ bc1,
                      const float* __restrict__ Wc2, const float* __restrict__ bc2,
                      const float* __restrict__ Wc3, const float* __restrict__ bc3,
                      float* __restrict__ out) {
    int g = blockIdx.x, t = threadIdx.x;
    __shared__ float p[256], q1[16], q2[64];
    p[t] = g_pooled[g * 256 + t];
    __syncthreads();
    float* o1 = out;
    float* o2 = out + 256 * 16;
    float* o3 = out + 256 * 16 + 256 * 64;

    if (t < 16) {
        float s = bc1[t];
        for (int k = 0; k < 256; k++) s += p[k] * Wc1[k * 16 + t];
        q1[t] = s;
        o1[g * 16 + t] = s;
    }
    __syncthreads();
    if (t == 0) {
        float m = q1[0];
        for (int i = 1; i < 16; i++) m = fmaxf(m, q1[i]);
        float sum = 0.f;
        for (int i = 0; i < 16; i++) { q1[i] = expf(q1[i] - m); sum += q1[i]; }
        float inv = 1.f / sum;
        for (int i = 0; i < 16; i++) q1[i] *= inv;
    }
    __syncthreads();
    if (t < 64) {
        float s = bc2[t];
        for (int k = 0; k < 256; k++) s += p[k] * Wc2[k * 64 + t];
        for (int k = 0; k < 16; k++) s += q1[k] * Wc2[(256 + k) * 64 + t];
        q2[t] = s;
        o2[g * 64 + t] = s;
    }
    __syncthreads();
    if (t == 0) {
        float m = q2[0];
        for (int i = 1; i < 64; i++) m = fmaxf(m, q2[i]);
        float sum = 0.f;
        for (int i = 0; i < 64; i++) { q2[i] = expf(q2[i] - m); sum += q2[i]; }
        float inv = 1.f / sum;
        for (int i = 0; i < 64; i++) q2[i] *= inv;
    }
    __syncthreads();
    {
        float s = bc3[t];
        for (int k = 0; k < 256; k++) s += p[k] * Wc3[k * 256 + t];
        for (int k = 0; k < 64; k++) s += q2[k] * Wc3[(256 + k) * 256 + t];
        o3[g * 256 + t] = s;
    }
}

// ---------------- launch ----------------
extern "C" void kernel_launch(void* const* d_in, const int* in_sizes, int n_in,
                              void* d_out, int out_size) {
    const float* x     = (const float*)d_in[0];
    const int*   ei    = (const int*)d_in[1];
    const int*   batch = (const int*)d_in[2];
    const float* W1 = (const float*)d_in[3],  *b1 = (const float*)d_in[4];
    const float* W2 = (const float*)d_in[5],  *b2 = (const float*)d_in[6];
    const float* W3 = (const float*)d_in[7],  *b3 = (const float*)d_in[8];
    const float* Wc1 = (const float*)d_in[9],  *bc1 = (const float*)d_in[10];
    const float* Wc2 = (const float*)d_in[11], *bc2 = (const float*)d_in[12];
    const float* Wc3 = (const float*)d_in[13], *bc3 = (const float*)d_in[14];
    float* out = (float*)d_out;

    k_zero<<<(NN + 255) / 256, 256>>>();
    k_hist<<<NE / 256, 256>>>(ei);
    k_scan<<<1, 1024>>>();
    k_dinv<<<(NN + 255) / 256, 256>>>();
    k_build<<<NE / 256, 256>>>(ei);

    dim3 gg(2, (NN + 127) / 128);  // (2, 391)
    k_gemm_tc<<<gg, 256>>>(x, 1, W1, INDIM);
    k_agg<<<(NN * 32) / 256, 256>>>(b1, 1);
    k_gemm_tc<<<gg, 256>>>(nullptr, 0, W2, HID);
    k_agg<<<(NN * 32) / 256, 256>>>(b2, 1);
    k_gemm_tc<<<gg, 256>>>(nullptr, 0, W3, HID);
    k_agg<<<(NN * 32) / 256, 256>>>(b3, 0);

    k_pool<<<NG, 256>>>(batch);
    k_cls<<<NG, 256>>>(Wc1, bc1, Wc2, bc2, Wc3, bc3, out);
}

// round 5
// speedup vs baseline: 1.8202x; 1.3674x over previous
#include <cuda_runtime.h>
#include <stdint.h>

#define NN 50000
#define NE 800000
#define NG 256
#define INDIM 300
#define HID 256

// ---------------- scratch (device globals; no allocation allowed) ----------------
__device__ __align__(16) float g_t[(size_t)NN * HID];   // transformed (h @ W)
__device__ __align__(16) float g_a[(size_t)NN * HID];   // aggregated output
__device__ float g_dinv[NN];
__device__ int   g_cnt[NN];
__device__ int   g_rowptr[NN + 1];
__device__ int   g_cursor[NN];
__device__ int   g_csr_src[NE];
__device__ float g_csr_w[NE];
__device__ float g_pooled[NG * HID];

// ---------------- graph preprocessing ----------------
__global__ void k_zero() {
    int i = blockIdx.x * blockDim.x + threadIdx.x;
    if (i < NN) { g_cnt[i] = 0; g_cursor[i] = 0; }
}

__global__ void k_hist(const int* __restrict__ ei) {
    int e = blockIdx.x * blockDim.x + threadIdx.x;
    if (e < NE) {
        int d = ei[NE + e];
        if (d >= 0 && d < NN) atomicAdd(&g_cnt[d], 1);
    }
}

__global__ void k_scan() {
    const int CH = (NN + 1023) / 1024;  // 49
    __shared__ int part[1024];
    int t = threadIdx.x;
    int begin = t * CH;
    int end = begin + CH; if (end > NN) end = NN; if (begin > NN) begin = NN;
    int s = 0;
    for (int i = begin; i < end; i++) s += g_cnt[i];
    part[t] = s;
    __syncthreads();
    if (t == 0) {
        int run = 0;
        for (int i = 0; i < 1024; i++) { int v = part[i]; part[i] = run; run += v; }
    }
    __syncthreads();
    int run = part[t];
    for (int i = begin; i < end; i++) { g_rowptr[i] = run; run += g_cnt[i]; }
    if (t == 1023) g_rowptr[NN] = run;
}

__global__ void k_dinv() {
    int i = blockIdx.x * blockDim.x + threadIdx.x;
    if (i < NN) g_dinv[i] = rsqrtf((float)(g_cnt[i] + 1));
}

__global__ void k_build(const int* __restrict__ ei) {
    int e = blockIdx.x * blockDim.x + threadIdx.x;
    if (e >= NE) return;
    int s = ei[e];
    int d = ei[NE + e];
    if (s < 0 || s >= NN || d < 0 || d >= NN) return;
    int pos = g_rowptr[d] + atomicAdd(&g_cursor[d], 1);
    g_csr_src[pos] = s;
    g_csr_w[pos] = g_dinv[s] * g_dinv[d];
}

// ---------------- tf32 tensor-core GEMM, 2-stage cp.async pipeline ----------------
__device__ __forceinline__ void cp16(uint32_t dst, const void* src, int srcbytes) {
    asm volatile("cp.async.cg.shared.global [%0], [%1], 16, %2;\n"
                 :: "r"(dst), "l"(src), "r"(srcbytes));
}
__device__ __forceinline__ void cp_commit() {
    asm volatile("cp.async.commit_group;\n");
}
__device__ __forceinline__ void cp_wait1() {
    asm volatile("cp.async.wait_group 1;\n");
}

// block tile 128x128, BK=16, 256 threads = 8 warps (4x2), warp tile 32x64
__global__ void __launch_bounds__(256) k_gemm_tc(const float* __restrict__ Aext, int use_ext,
                                                 const float* __restrict__ B, int K) {
    const float* A = use_ext ? Aext : (const float*)g_a;
    __shared__ uint32_t As[2][128][20];   // [buf][m][k]
    __shared__ uint32_t Bs[2][16][136];   // [buf][k][n]

    int bm = blockIdx.y * 128, bn = blockIdx.x * 128;
    int tid = threadIdx.x;
    int wid = tid >> 5, lane = tid & 31;
    int wr = wid >> 1, wc = wid & 1;
    int gid = lane >> 2, tig = lane & 3;

    // per-thread load coordinates (2 chunks each for A and B)
    int a_row0 = tid >> 2, a_kq0 = (tid & 3) << 2;
    int a_row1 = (tid + 256) >> 2, a_kq1 = ((tid + 256) & 3) << 2;
    int b_kk0 = tid >> 5, b_n40 = (tid & 31) << 2;
    int b_kk1 = (tid + 256) >> 5, b_n41 = ((tid + 256) & 31) << 2;

    float acc[2][8][4];
    #pragma unroll
    for (int i = 0; i < 2; i++)
        #pragma unroll
        for (int j = 0; j < 8; j++)
            #pragma unroll
            for (int l = 0; l < 4; l++) acc[i][j][l] = 0.f;

    int T = (K + 15) / 16;

    // tile loader: raw fp32 bits (tf32 fast path), zfill for OOB
    auto load_tile = [&](int tile, int buf) {
        int k0 = tile * 16;
        {
            int grow = bm + a_row0;
            int rem = K - (k0 + a_kq0);
            int bytes = (grow < NN && rem > 0) ? (rem >= 4 ? 16 : rem * 4) : 0;
            const float* src = (bytes > 0) ? (A + (size_t)grow * K + k0 + a_kq0) : A;
            cp16((uint32_t)__cvta_generic_to_shared(&As[buf][a_row0][a_kq0]), src, bytes);
        }
        {
            int grow = bm + a_row1;
            int rem = K - (k0 + a_kq1);
            int bytes = (grow < NN && rem > 0) ? (rem >= 4 ? 16 : rem * 4) : 0;
            const float* src = (bytes > 0) ? (A + (size_t)grow * K + k0 + a_kq1) : A;
            cp16((uint32_t)__cvta_generic_to_shared(&As[buf][a_row1][a_kq1]), src, bytes);
        }
        {
            int gk = k0 + b_kk0;
            int bytes = (gk < K) ? 16 : 0;
            const float* src = (bytes > 0) ? (B + (size_t)gk * 256 + bn + b_n40) : B;
            cp16((uint32_t)__cvta_generic_to_shared(&Bs[buf][b_kk0][b_n40]), src, bytes);
        }
        {
            int gk = k0 + b_kk1;
            int bytes = (gk < K) ? 16 : 0;
            const float* src = (bytes > 0) ? (B + (size_t)gk * 256 + bn + b_n41) : B;
            cp16((uint32_t)__cvta_generic_to_shared(&Bs[buf][b_kk1][b_n41]), src, bytes);
        }
    };

    load_tile(0, 0);
    cp_commit();

    for (int it = 0; it < T; it++) {
        if (it + 1 < T) load_tile(it + 1, (it + 1) & 1);
        cp_commit();
        cp_wait1();
        __syncthreads();

        int buf = it & 1;
        #pragma unroll
        for (int ks = 0; ks < 16; ks += 8) {
            uint32_t a[2][4], b[8][2];
            #pragma unroll
            for (int mt = 0; mt < 2; mt++) {
                int r = wr * 32 + mt * 16;
                a[mt][0] = As[buf][r + gid][ks + tig];
                a[mt][1] = As[buf][r + gid + 8][ks + tig];
                a[mt][2] = As[buf][r + gid][ks + tig + 4];
                a[mt][3] = As[buf][r + gid + 8][ks + tig + 4];
            }
            #pragma unroll
            for (int nt = 0; nt < 8; nt++) {
                int c = wc * 64 + nt * 8 + gid;
                b[nt][0] = Bs[buf][ks + tig][c];
                b[nt][1] = Bs[buf][ks + tig + 4][c];
            }
            #pragma unroll
            for (int mt = 0; mt < 2; mt++)
                #pragma unroll
                for (int nt = 0; nt < 8; nt++) {
                    asm volatile(
                        "mma.sync.aligned.m16n8k8.row.col.f32.tf32.tf32.f32 "
                        "{%0,%1,%2,%3}, {%4,%5,%6,%7}, {%8,%9}, {%0,%1,%2,%3};"
                        : "+f"(acc[mt][nt][0]), "+f"(acc[mt][nt][1]),
                          "+f"(acc[mt][nt][2]), "+f"(acc[mt][nt][3])
                        : "r"(a[mt][0]), "r"(a[mt][1]), "r"(a[mt][2]), "r"(a[mt][3]),
                          "r"(b[nt][0]), "r"(b[nt][1]));
                }
        }
        __syncthreads();
    }

    // ---- store ----
    #pragma unroll
    for (int mt = 0; mt < 2; mt++) {
        #pragma unroll
        for (int nt = 0; nt < 8; nt++) {
            int r0 = bm + wr * 32 + mt * 16 + gid;
            int cc = bn + wc * 64 + nt * 8 + tig * 2;
            if (r0 < NN) {
                float2 v; v.x = acc[mt][nt][0]; v.y = acc[mt][nt][1];
                *(float2*)(g_t + (size_t)r0 * 256 + cc) = v;
            }
            if (r0 + 8 < NN) {
                float2 v; v.x = acc[mt][nt][2]; v.y = acc[mt][nt][3];
                *(float2*)(g_t + (size_t)(r0 + 8) * 256 + cc) = v;
            }
        }
    }
}

// ---------------- aggregation ----------------
__global__ void k_agg(const float* __restrict__ bias, int relu) {
    int gw = (blockIdx.x * blockDim.x + threadIdx.x) >> 5;
    int lane = threadIdx.x & 31;
    if (gw >= NN) return;
    int n = gw;
    float dn = g_dinv[n];
    float sw = dn * dn;
    const float4* trow = (const float4*)(g_t + (size_t)n * 256);
    float4 a0 = trow[lane], a1 = trow[lane + 32];
    a0.x *= sw; a0.y *= sw; a0.z *= sw; a0.w *= sw;
    a1.x *= sw; a1.y *= sw; a1.z *= sw; a1.w *= sw;
    int beg = g_rowptr[n], end = g_rowptr[n + 1];
    for (int i = beg; i < end; i++) {
        int s = g_csr_src[i];
        float w = g_csr_w[i];
        const float4* srow = (const float4*)(g_t + (size_t)s * 256);
        float4 v0 = srow[lane], v1 = srow[lane + 32];
        a0.x += w * v0.x; a0.y += w * v0.y; a0.z += w * v0.z; a0.w += w * v0.w;
        a1.x += w * v1.x; a1.y += w * v1.y; a1.z += w * v1.z; a1.w += w * v1.w;
    }
    float4 b0 = ((const float4*)bias)[lane];
    float4 b1 = ((const float4*)bias)[lane + 32];
    a0.x += b0.x; a0.y += b0.y; a0.z += b0.z; a0.w += b0.w;
    a1.x += b1.x; a1.y += b1.y; a1.z += b1.z; a1.w += b1.w;
    if (relu) {
        a0.x = fmaxf(a0.x, 0.f); a0.y = fmaxf(a0.y, 0.f);
        a0.z = fmaxf(a0.z, 0.f); a0.w = fmaxf(a0.w, 0.f);
        a1.x = fmaxf(a1.x, 0.f); a1.y = fmaxf(a1.y, 0.f);
        a1.w = fmaxf(a1.w, 0.f); a1.z = fmaxf(a1.z, 0.f);
    }
    float4* orow = (float4*)(g_a + (size_t)n * 256);
    orow[lane] = a0; orow[lane + 32] = a1;
}

// ---------------- global mean pool (batch is sorted int32) ----------------
__global__ void k_pool(const int* __restrict__ batch) {
    int g = blockIdx.x;
    int c = threadIdx.x;  // 256 threads
    __shared__ int slo, shi;
    if (c == 0) {
        int l = 0, r = NN;
        while (l < r) { int m = (l + r) >> 1; if (batch[m] < g) l = m + 1; else r = m; }
        slo = l;
        l = 0; r = NN;
        while (l < r) { int m = (l + r) >> 1; if (batch[m] < g + 1) l = m + 1; else r = m; }
        shi = l;
    }
    __syncthreads();
    int lo = slo, hi = shi;
    float s = 0.f;
    for (int n = lo; n < hi; n++) s += g_a[(size_t)n * 256 + c];
    int cnt = hi - lo;
    float inv = (cnt > 0) ? (1.0f / (float)cnt) : 1.0f;
    g_pooled[g * 256 + c] = s * inv;
}

// ---------------- classifier: one block per graph ----------------
__global__ void k_cls(const float* __restrict__ Wc1, const float* __restrict__ bc1,
                      const float* __restrict__ Wc2, const float* __restrict__ bc2,
                      const float* __restrict__ Wc3, const float* __restrict__ bc3,
                      float* __restrict__ out) {
    int g = blockIdx.x, t = threadIdx.x;
    __shared__ float p[256], q1[16], q2[64];
    p[t] = g_pooled[g * 256 + t];
    __syncthreads();
    float* o1 = out;
    float* o2 = out + 256 * 16;
    float* o3 = out + 256 * 16 + 256 * 64;

    if (t < 16) {
        float s = bc1[t];
        for (int k = 0; k < 256; k++) s += p[k] * Wc1[k * 16 + t];
        q1[t] = s;
        o1[g * 16 + t] = s;
    }
    __syncthreads();
    if (t == 0) {
        float m = q1[0];
        for (int i = 1; i < 16; i++) m = fmaxf(m, q1[i]);
        float sum = 0.f;
        for (int i = 0; i < 16; i++) { q1[i] = expf(q1[i] - m); sum += q1[i]; }
        float inv = 1.f / sum;
        for (int i = 0; i < 16; i++) q1[i] *= inv;
    }
    __syncthreads();
    if (t < 64) {
        float s = bc2[t];
        for (int k = 0; k < 256; k++) s += p[k] * Wc2[k * 64 + t];
        for (int k = 0; k < 16; k++) s += q1[k] * Wc2[(256 + k) * 64 + t];
        q2[t] = s;
        o2[g * 64 + t] = s;
    }
    __syncthreads();
    if (t == 0) {
        float m = q2[0];
        for (int i = 1; i < 64; i++) m = fmaxf(m, q2[i]);
        float sum = 0.f;
        for (int i = 0; i < 64; i++) { q2[i] = expf(q2[i] - m); sum += q2[i]; }
        float inv = 1.f / sum;
        for (int i = 0; i < 64; i++) q2[i] *= inv;
    }
    __syncthreads();
    {
        float s = bc3[t];
        for (int k = 0; k < 256; k++) s += p[k] * Wc3[k * 256 + t];
        for (int k = 0; k < 64; k++) s += q2[k] * Wc3[(256 + k) * 256 + t];
        o3[g * 256 + t] = s;
    }
}

// ---------------- launch ----------------
extern "C" void kernel_launch(void* const* d_in, const int* in_sizes, int n_in,
                              void* d_out, int out_size) {
    const float* x     = (const float*)d_in[0];
    const int*   ei    = (const int*)d_in[1];
    const int*   batch = (const int*)d_in[2];
    const float* W1 = (const float*)d_in[3],  *b1 = (const float*)d_in[4];
    const float* W2 = (const float*)d_in[5],  *b2 = (const float*)d_in[6];
    const float* W3 = (const float*)d_in[7],  *b3 = (const float*)d_in[8];
    const float* Wc1 = (const float*)d_in[9],  *bc1 = (const float*)d_in[10];
    const float* Wc2 = (const float*)d_in[11], *bc2 = (const float*)d_in[12];
    const float* Wc3 = (const float*)d_in[13], *bc3 = (const float*)d_in[14];
    float* out = (float*)d_out;

    k_zero<<<(NN + 255) / 256, 256>>>();
    k_hist<<<NE / 256, 256>>>(ei);
    k_scan<<<1, 1024>>>();
    k_dinv<<<(NN + 255) / 256, 256>>>();
    k_build<<<NE / 256, 256>>>(ei);

    dim3 gg(2, (NN + 127) / 128);  // (2, 391)
    k_gemm_tc<<<gg, 256>>>(x, 1, W1, INDIM);
    k_agg<<<(NN * 32) / 256, 256>>>(b1, 1);
    k_gemm_tc<<<gg, 256>>>(nullptr, 0, W2, HID);
    k_agg<<<(NN * 32) / 256, 256>>>(b2, 1);
    k_gemm_tc<<<gg, 256>>>(nullptr, 0, W3, HID);
    k_agg<<<(NN * 32) / 256, 256>>>(b3, 0);

    k_pool<<<NG, 256>>>(batch);
    k_cls<<<NG, 256>>>(Wc1, bc1, Wc2, bc2, Wc3, bc3, out);
}